// round 12
// baseline (speedup 1.0000x reference)
#include <cuda_runtime.h>
#include <cuda_fp16.h>
#include <stdint.h>

#define HQ 16
#define HKV 8
#define D 128
#define BQ 128
#define BKV 64
#define NT 256
#define TMAX 4096
// attention scale with log2(e) folded in: exp(x) = exp2(x*log2e)
#define QSCALE (0.08838834764831845f * 1.4426950408889634f)

#define RSTR 272   // bytes per smem row (136 fp16: 128 data + 8 pad)

// SMEM byte offsets: Q | stage0 | stage1   (2-stage cp.async pipeline)
#define SM_QH 0                         // 128*272
#define SM_ST(i) (34816 + (i) * 34816)  // each: K 64*272 | V 64*272
#define SM_V_OFF 17408
#define SMEM_BYTES (34816 * 3)          // 104448  -> 2 CTAs/SM

// preconverted fp16 K/V (graph-safe scratch)
__device__ __half g_k16[(size_t)TMAX * HKV * D];
__device__ __half g_v16[(size_t)TMAX * HKV * D];

__device__ __forceinline__ uint32_t smem_u32(const void* p) {
    uint32_t a;
    asm("{ .reg .u64 t; cvta.to.shared.u64 t, %1; cvt.u32.u64 %0, t; }" : "=r"(a) : "l"(p));
    return a;
}
__device__ __forceinline__ void ldsm_x4(uint32_t& r0, uint32_t& r1, uint32_t& r2,
                                        uint32_t& r3, uint32_t addr) {
    asm volatile("ldmatrix.sync.aligned.m8n8.x4.shared.b16 {%0,%1,%2,%3}, [%4];"
                 : "=r"(r0), "=r"(r1), "=r"(r2), "=r"(r3) : "r"(addr));
}
__device__ __forceinline__ void ldsm_x4t(uint32_t& r0, uint32_t& r1, uint32_t& r2,
                                         uint32_t& r3, uint32_t addr) {
    asm volatile("ldmatrix.sync.aligned.m8n8.x4.trans.shared.b16 {%0,%1,%2,%3}, [%4];"
                 : "=r"(r0), "=r"(r1), "=r"(r2), "=r"(r3) : "r"(addr));
}
__device__ __forceinline__ void mma16816(float* c, uint32_t a0, uint32_t a1,
                                         uint32_t a2, uint32_t a3,
                                         uint32_t b0, uint32_t b1) {
    asm volatile("mma.sync.aligned.m16n8k16.row.col.f32.f16.f16.f32 "
                 "{%0,%1,%2,%3}, {%4,%5,%6,%7}, {%8,%9}, {%0,%1,%2,%3};"
                 : "+f"(c[0]), "+f"(c[1]), "+f"(c[2]), "+f"(c[3])
                 : "r"(a0), "r"(a1), "r"(a2), "r"(a3), "r"(b0), "r"(b1));
}
__device__ __forceinline__ uint32_t cvt2h(float x, float y) {
    __half2 H = __floats2half2_rn(x, y);
    return *(uint32_t*)&H;
}

// ---- pre-pass: fp32 K/V -> fp16 global buffers ----
__global__ void __launch_bounds__(256, 4)
cvt_kv_kernel(const float* __restrict__ k, const float* __restrict__ v, int n4)
{
    int i = blockIdx.x * blockDim.x + threadIdx.x;
    if (i < n4) {
        float4 a = ((const float4*)k)[i];
        ((__half2*)g_k16)[2 * i]     = __floats2half2_rn(a.x, a.y);
        ((__half2*)g_k16)[2 * i + 1] = __floats2half2_rn(a.z, a.w);
        float4 b = ((const float4*)v)[i];
        ((__half2*)g_v16)[2 * i]     = __floats2half2_rn(b.x, b.y);
        ((__half2*)g_v16)[2 * i + 1] = __floats2half2_rn(b.z, b.w);
    }
}

__global__ void __launch_bounds__(NT, 2)
fa_hmma_occ2_kernel(const float* __restrict__ q,
                    const int*   __restrict__ pos,
                    float*       __restrict__ out)
{
    extern __shared__ __align__(16) unsigned char smem[];
    const uint32_t sb = smem_u32(smem);

    const int tid  = threadIdx.x;
    const int wid  = tid >> 5;
    const int lane = tid & 31;
    const int bq0  = (gridDim.x - 1 - blockIdx.x) * BQ;   // longest-first
    const int h    = blockIdx.y;
    const int kvh  = h >> 1;

    const int kb0 = (bq0 - pos[bq0]) & ~(BKV - 1);

    // cp.async duty: (tensor, row, half) unique per thread
    const int cp_tensor = tid & 1;
    const int cp_row    = (tid >> 1) & 63;
    const int cp_half   = tid >> 7;
    const __half* cp_src0 = (cp_tensor ? g_v16 : g_k16)
                            + ((size_t)cp_row * HKV + kvh) * D + cp_half * 64;
    const uint32_t cp_dst_off = (uint32_t)(cp_tensor * SM_V_OFF
                                           + cp_row * RSTR + cp_half * 128);

    // ---- prologue: prefetch tile 0 into stage 0 (overlaps Q staging) ----
    {
        const __half* src = cp_src0 + (size_t)kb0 * (HKV * D);
        const uint32_t dst = sb + SM_ST(0) + cp_dst_off;
        #pragma unroll
        for (int u = 0; u < 8; u++)
            asm volatile("cp.async.cg.shared.global [%0], [%1], 16;"
                         :: "r"(dst + u * 16), "l"(src + u * 8));
        asm volatile("cp.async.commit_group;" ::: "memory");
    }

    // ---- stage Q (scaled by QSCALE*log2e, single fp16) ----
    {
        const int tok  = tid >> 1;
        const int dseg = (tid & 1) * 64;
        const float* qr = q + (size_t)(bq0 + tok) * (HQ * D) + h * D + dseg;
        unsigned char* qhrow = smem + SM_QH + tok * RSTR + dseg * 2;
        #pragma unroll
        for (int c8 = 0; c8 < 8; c8++) {
            float4 a = *(const float4*)(qr + c8 * 8);
            float4 b = *(const float4*)(qr + c8 * 8 + 4);
            *(uint4*)(qhrow + c8 * 16) =
                make_uint4(cvt2h(a.x * QSCALE, a.y * QSCALE),
                           cvt2h(a.z * QSCALE, a.w * QSCALE),
                           cvt2h(b.x * QSCALE, b.y * QSCALE),
                           cvt2h(b.z * QSCALE, b.w * QSCALE));
        }
    }

    // per-lane row metadata (C-fragment rows)
    const int gi0  = bq0 + 16 * wid + (lane >> 2);
    const int gi1  = gi0 + 8;
    const int rsv0 = gi0 - pos[gi0];
    const int rsv1 = gi1 - pos[gi1];

    // fragment smem byte-offset bases (per lane)
    const uint32_t qa_off = (uint32_t)((16 * wid + (lane & 15)) * RSTR + (lane >> 4) * 16);
    const uint32_t kb_off = (uint32_t)((((lane >> 4) & 1) * 8 + (lane & 7)) * RSTR
                                       + ((lane >> 3) & 1) * 16);
    const uint32_t vb_off = (uint32_t)((((lane >> 3) & 1) * 8 + (lane & 7)) * RSTR
                                       + SM_V_OFF + ((lane >> 4) & 1) * 16);

    float O[16][4];
    #pragma unroll
    for (int n = 0; n < 16; n++)
        #pragma unroll
        for (int e = 0; e < 4; e++) O[n][e] = 0.0f;
    float lsum0 = 0.0f, lsum1 = 0.0f;

    int it = 0;
    for (int kb = kb0; kb < bq0 + BQ; kb += BKV, ++it) {
        // tile it's copy is the only outstanding group: finish it, make visible
        asm volatile("cp.async.wait_group 0;" ::: "memory");
        __syncthreads();   // copies visible; all prev-tile reads complete

        const uint32_t stage = sb + SM_ST(it & 1);
        if (kb + BKV < bq0 + BQ) {
            // buffer (it+1)&1 was last read at iter it-1 -> free (barrier above)
            const __half* src = cp_src0 + (size_t)(kb + BKV) * (HKV * D);
            const uint32_t dst = sb + SM_ST((it + 1) & 1) + cp_dst_off;
            #pragma unroll
            for (int u = 0; u < 8; u++)
                asm volatile("cp.async.cg.shared.global [%0], [%1], 16;"
                             :: "r"(dst + u * 16), "l"(src + u * 8));
            asm volatile("cp.async.commit_group;" ::: "memory");
        }

        // ---- S = Q K^T : single fp16 term ----
        float S[8][4];
        #pragma unroll
        for (int n = 0; n < 8; n++)
            #pragma unroll
            for (int e = 0; e < 4; e++) S[n][e] = 0.0f;

        #pragma unroll
        for (int kk = 0; kk < 8; kk++) {
            uint32_t qh0,qh1,qh2,qh3;
            ldsm_x4(qh0,qh1,qh2,qh3, sb + SM_QH + qa_off + kk * 32);
            uint32_t kf[4][4];
            #pragma unroll
            for (int np = 0; np < 4; np++)
                ldsm_x4(kf[np][0], kf[np][1], kf[np][2], kf[np][3],
                        stage + kb_off + np * (16 * RSTR) + kk * 32);
            #pragma unroll
            for (int np = 0; np < 4; np++) {
                mma16816(S[2*np],   qh0,qh1,qh2,qh3, kf[np][0], kf[np][1]);
                mma16816(S[2*np+1], qh0,qh1,qh2,qh3, kf[np][2], kf[np][3]);
            }
        }

        // ---- mask + exp2 (log2e pre-folded; no online max) ----
        #pragma unroll
        for (int n = 0; n < 8; n++) {
            const int gj = kb + n * 8 + 2 * (lane & 3);
            float p0 = (gj     <= gi0 && gj     >= rsv0) ? exp2f(S[n][0]) : 0.0f;
            float p1 = (gj + 1 <= gi0 && gj + 1 >= rsv0) ? exp2f(S[n][1]) : 0.0f;
            float p2 = (gj     <= gi1 && gj     >= rsv1) ? exp2f(S[n][2]) : 0.0f;
            float p3 = (gj + 1 <= gi1 && gj + 1 >= rsv1) ? exp2f(S[n][3]) : 0.0f;
            lsum0 += p0 + p1;
            lsum1 += p2 + p3;
            S[n][0] = p0; S[n][1] = p1; S[n][2] = p2; S[n][3] = p3;
        }

        // ---- O += P V : single fp16 term, P frag from C regs ----
        #pragma unroll
        for (int kc = 0; kc < 4; kc++) {
            uint32_t ah0 = cvt2h(S[2*kc][0],   S[2*kc][1]);
            uint32_t ah1 = cvt2h(S[2*kc][2],   S[2*kc][3]);
            uint32_t ah2 = cvt2h(S[2*kc+1][0], S[2*kc+1][1]);
            uint32_t ah3 = cvt2h(S[2*kc+1][2], S[2*kc+1][3]);
            const uint32_t vrow = vb_off + kc * (16 * RSTR);
            #pragma unroll
            for (int p = 0; p < 8; p++) {
                uint32_t vf0, vf1, vf2, vf3;
                ldsm_x4t(vf0, vf1, vf2, vf3, stage + vrow + p * 32);
                mma16816(O[2*p],   ah0,ah1,ah2,ah3, vf0, vf1);
                mma16816(O[2*p+1], ah0,ah1,ah2,ah3, vf2, vf3);
            }
        }
    }

    // ---- row-sum reduce across quad, normalize, store ----
    lsum0 += __shfl_xor_sync(0xffffffffu, lsum0, 1);
    lsum0 += __shfl_xor_sync(0xffffffffu, lsum0, 2);
    lsum1 += __shfl_xor_sync(0xffffffffu, lsum1, 1);
    lsum1 += __shfl_xor_sync(0xffffffffu, lsum1, 2);
    const float inv0 = 1.0f / lsum0;
    const float inv1 = 1.0f / lsum1;

    float* o0 = out + (size_t)gi0 * (HQ * D) + h * D + 2 * (lane & 3);
    float* o1 = out + (size_t)gi1 * (HQ * D) + h * D + 2 * (lane & 3);
    #pragma unroll
    for (int n = 0; n < 16; n++) {
        *(float2*)(o0 + n * 8) = make_float2(O[n][0] * inv0, O[n][1] * inv0);
        *(float2*)(o1 + n * 8) = make_float2(O[n][2] * inv1, O[n][3] * inv1);
    }
}

extern "C" void kernel_launch(void* const* d_in, const int* in_sizes, int n_in,
                              void* d_out, int out_size)
{
    const float* q   = (const float*)d_in[0];
    const float* k   = (const float*)d_in[1];
    const float* v   = (const float*)d_in[2];
    const int*   pos = (const int*)d_in[3];
    float* out = (float*)d_out;

    const int T  = in_sizes[3];
    const int n4 = T * HKV * D / 4;

    cvt_kv_kernel<<<(n4 + 255) / 256, 256>>>(k, v, n4);

    cudaFuncSetAttribute(fa_hmma_occ2_kernel,
                         cudaFuncAttributeMaxDynamicSharedMemorySize,
                         SMEM_BYTES);
    dim3 grid(T / BQ, HQ);
    fa_hmma_occ2_kernel<<<grid, NT, SMEM_BYTES>>>(q, pos, out);
}

// round 13
// speedup vs baseline: 1.1063x; 1.1063x over previous
#include <cuda_runtime.h>
#include <cuda_fp16.h>
#include <stdint.h>

#define HQ 16
#define HKV 8
#define D 128
#define BQ 128
#define BKV 128        // staged kv rows per pipeline step (2 x 64 sub-tiles)
#define NT 256
#define TMAX 4096
// attention scale with log2(e) folded in: exp(x) = exp2(x*log2e)
#define QSCALE (0.08838834764831845f * 1.4426950408889634f)

#define RSTR 272       // bytes per smem row (136 fp16: 128 data + 8 pad)

// SMEM: Q | stage0 | stage1 ; stage = K 128*272 | V 128*272
#define SM_QH 0
#define SM_VOF 34816                      // V offset within a stage
#define SM_ST(i) (34816 + (i) * 69632)
#define SMEM_BYTES (34816 + 2 * 69632)    // 174080

// preconverted fp16 K/V (graph-safe scratch)
__device__ __half g_k16[(size_t)TMAX * HKV * D];
__device__ __half g_v16[(size_t)TMAX * HKV * D];

__device__ __forceinline__ uint32_t smem_u32(const void* p) {
    uint32_t a;
    asm("{ .reg .u64 t; cvta.to.shared.u64 t, %1; cvt.u32.u64 %0, t; }" : "=r"(a) : "l"(p));
    return a;
}
__device__ __forceinline__ void ldsm_x4(uint32_t& r0, uint32_t& r1, uint32_t& r2,
                                        uint32_t& r3, uint32_t addr) {
    asm volatile("ldmatrix.sync.aligned.m8n8.x4.shared.b16 {%0,%1,%2,%3}, [%4];"
                 : "=r"(r0), "=r"(r1), "=r"(r2), "=r"(r3) : "r"(addr));
}
__device__ __forceinline__ void ldsm_x4t(uint32_t& r0, uint32_t& r1, uint32_t& r2,
                                         uint32_t& r3, uint32_t addr) {
    asm volatile("ldmatrix.sync.aligned.m8n8.x4.trans.shared.b16 {%0,%1,%2,%3}, [%4];"
                 : "=r"(r0), "=r"(r1), "=r"(r2), "=r"(r3) : "r"(addr));
}
__device__ __forceinline__ void mma16816(float* c, uint32_t a0, uint32_t a1,
                                         uint32_t a2, uint32_t a3,
                                         uint32_t b0, uint32_t b1) {
    asm volatile("mma.sync.aligned.m16n8k16.row.col.f32.f16.f16.f32 "
                 "{%0,%1,%2,%3}, {%4,%5,%6,%7}, {%8,%9}, {%0,%1,%2,%3};"
                 : "+f"(c[0]), "+f"(c[1]), "+f"(c[2]), "+f"(c[3])
                 : "r"(a0), "r"(a1), "r"(a2), "r"(a3), "r"(b0), "r"(b1));
}
__device__ __forceinline__ uint32_t cvt2h(float x, float y) {
    __half2 H = __floats2half2_rn(x, y);
    return *(uint32_t*)&H;
}

// ---- pre-pass: fp32 K/V -> fp16 global buffers ----
__global__ void __launch_bounds__(256, 4)
cvt_kv_kernel(const float* __restrict__ k, const float* __restrict__ v, int n4)
{
    int i = blockIdx.x * blockDim.x + threadIdx.x;
    if (i < n4) {
        float4 a = ((const float4*)k)[i];
        ((__half2*)g_k16)[2 * i]     = __floats2half2_rn(a.x, a.y);
        ((__half2*)g_k16)[2 * i + 1] = __floats2half2_rn(a.z, a.w);
        float4 b = ((const float4*)v)[i];
        ((__half2*)g_v16)[2 * i]     = __floats2half2_rn(b.x, b.y);
        ((__half2*)g_v16)[2 * i + 1] = __floats2half2_rn(b.z, b.w);
    }
}

__global__ void __launch_bounds__(NT, 1)
fa_hmma_bk128_kernel(const float* __restrict__ q,
                     const int*   __restrict__ pos,
                     float*       __restrict__ out)
{
    extern __shared__ __align__(16) unsigned char smem[];
    const uint32_t sb = smem_u32(smem);

    const int tid  = threadIdx.x;
    const int wid  = tid >> 5;
    const int lane = tid & 31;
    const int bq0  = (gridDim.x - 1 - blockIdx.x) * BQ;   // longest-first
    const int h    = blockIdx.y;
    const int kvh  = h >> 1;

    const int kb0 = (bq0 - pos[bq0]) & ~(BKV - 1);

    // cp.async duty: 2 chunks/thread; chunk c: tensor=c&1, row=(c>>1)&127, half=c>>8
    const int c0t = tid & 1;
    const int c0r = (tid >> 1) & 127;
    const __half* cp_src0a = (c0t ? g_v16 : g_k16) + ((size_t)c0r * HKV + kvh) * D;
    const __half* cp_src0b = (c0t ? g_v16 : g_k16) + ((size_t)c0r * HKV + kvh) * D + 64;
    const uint32_t cp_dsta = (uint32_t)(c0t * SM_VOF + c0r * RSTR);
    const uint32_t cp_dstb = cp_dsta + 128;

    // ---- prologue: prefetch tile 0 into stage 0 ----
    {
        const size_t off = (size_t)kb0 * (HKV * D);
        const uint32_t dst = sb + SM_ST(0);
        #pragma unroll
        for (int u = 0; u < 8; u++)
            asm volatile("cp.async.cg.shared.global [%0], [%1], 16;"
                         :: "r"(dst + cp_dsta + u * 16), "l"(cp_src0a + off + u * 8));
        #pragma unroll
        for (int u = 0; u < 8; u++)
            asm volatile("cp.async.cg.shared.global [%0], [%1], 16;"
                         :: "r"(dst + cp_dstb + u * 16), "l"(cp_src0b + off + u * 8));
        asm volatile("cp.async.commit_group;" ::: "memory");
    }

    // ---- stage Q (scaled, single fp16) ----
    {
        const int tok  = tid >> 1;
        const int dseg = (tid & 1) * 64;
        const float* qr = q + (size_t)(bq0 + tok) * (HQ * D) + h * D + dseg;
        unsigned char* qhrow = smem + SM_QH + tok * RSTR + dseg * 2;
        #pragma unroll
        for (int c8 = 0; c8 < 8; c8++) {
            float4 a = *(const float4*)(qr + c8 * 8);
            float4 b = *(const float4*)(qr + c8 * 8 + 4);
            *(uint4*)(qhrow + c8 * 16) =
                make_uint4(cvt2h(a.x * QSCALE, a.y * QSCALE),
                           cvt2h(a.z * QSCALE, a.w * QSCALE),
                           cvt2h(b.x * QSCALE, b.y * QSCALE),
                           cvt2h(b.z * QSCALE, b.w * QSCALE));
        }
    }

    // per-lane row metadata (C-fragment rows)
    const int gi0  = bq0 + 16 * wid + (lane >> 2);
    const int gi1  = gi0 + 8;
    const int rsv0 = gi0 - pos[gi0];
    const int rsv1 = gi1 - pos[gi1];
    // warp-uniform bounds for tile classification
    const int rowmin = bq0 + 16 * wid;
    const int rowmax = rowmin + 15;
    const int rsvmin = rowmin - pos[rowmin];
    const int rsvmax = rowmax - pos[rowmax];

    // fragment smem byte-offset bases (per lane)
    const uint32_t qa_off = (uint32_t)((16 * wid + (lane & 15)) * RSTR + (lane >> 4) * 16);
    const uint32_t kb_off = (uint32_t)((((lane >> 4) & 1) * 8 + (lane & 7)) * RSTR
                                       + ((lane >> 3) & 1) * 16);
    const uint32_t vb_off = (uint32_t)((((lane >> 3) & 1) * 8 + (lane & 7)) * RSTR
                                       + SM_VOF + ((lane >> 4) & 1) * 16);

    float O[16][4];
    #pragma unroll
    for (int n = 0; n < 16; n++)
        #pragma unroll
        for (int e = 0; e < 4; e++) O[n][e] = 0.0f;
    float lsum0 = 0.0f, lsum1 = 0.0f;

    int it = 0;
    for (int kb = kb0; kb < bq0 + BQ; kb += BKV, ++it) {
        asm volatile("cp.async.wait_group 0;" ::: "memory");
        __syncthreads();   // copies visible; prev-stage reads complete

        const uint32_t stage = sb + SM_ST(it & 1);
        if (kb + BKV < bq0 + BQ) {
            const size_t off = (size_t)(kb + BKV) * (HKV * D);
            const uint32_t dst = sb + SM_ST((it + 1) & 1);
            #pragma unroll
            for (int u = 0; u < 8; u++)
                asm volatile("cp.async.cg.shared.global [%0], [%1], 16;"
                             :: "r"(dst + cp_dsta + u * 16), "l"(cp_src0a + off + u * 8));
            #pragma unroll
            for (int u = 0; u < 8; u++)
                asm volatile("cp.async.cg.shared.global [%0], [%1], 16;"
                             :: "r"(dst + cp_dstb + u * 16), "l"(cp_src0b + off + u * 8));
            asm volatile("cp.async.commit_group;" ::: "memory");
        }

        #pragma unroll
        for (int sub = 0; sub < 2; sub++) {
            const int kbs = kb + sub * 64;
            // warp-uniform classification
            if (kbs > rowmax) continue;          // entirely beyond diagonal
            if (kbs + 63 < rsvmin) continue;     // entirely before segment
            const bool fast = (kbs + 63 <= rowmin) && (kbs >= rsvmax);
            const uint32_t subk = stage + (uint32_t)(sub * 64 * RSTR);

            // ---- S = Q K^T ----
            float S[8][4];
            #pragma unroll
            for (int n = 0; n < 8; n++)
                #pragma unroll
                for (int e = 0; e < 4; e++) S[n][e] = 0.0f;

            #pragma unroll
            for (int kk = 0; kk < 8; kk++) {
                uint32_t qh0,qh1,qh2,qh3;
                ldsm_x4(qh0,qh1,qh2,qh3, sb + SM_QH + qa_off + kk * 32);
                uint32_t kf[4][4];
                #pragma unroll
                for (int np = 0; np < 4; np++)
                    ldsm_x4(kf[np][0], kf[np][1], kf[np][2], kf[np][3],
                            subk + kb_off + np * (16 * RSTR) + kk * 32);
                #pragma unroll
                for (int np = 0; np < 4; np++) {
                    mma16816(S[2*np],   qh0,qh1,qh2,qh3, kf[np][0], kf[np][1]);
                    mma16816(S[2*np+1], qh0,qh1,qh2,qh3, kf[np][2], kf[np][3]);
                }
            }

            // ---- exp2 (fast: unmasked; else mask boundary) ----
            if (fast) {
                #pragma unroll
                for (int n = 0; n < 8; n++) {
                    float p0 = exp2f(S[n][0]);
                    float p1 = exp2f(S[n][1]);
                    float p2 = exp2f(S[n][2]);
                    float p3 = exp2f(S[n][3]);
                    lsum0 += p0 + p1;
                    lsum1 += p2 + p3;
                    S[n][0] = p0; S[n][1] = p1; S[n][2] = p2; S[n][3] = p3;
                }
            } else {
                #pragma unroll
                for (int n = 0; n < 8; n++) {
                    const int gj = kbs + n * 8 + 2 * (lane & 3);
                    float p0 = (gj     <= gi0 && gj     >= rsv0) ? exp2f(S[n][0]) : 0.0f;
                    float p1 = (gj + 1 <= gi0 && gj + 1 >= rsv0) ? exp2f(S[n][1]) : 0.0f;
                    float p2 = (gj     <= gi1 && gj     >= rsv1) ? exp2f(S[n][2]) : 0.0f;
                    float p3 = (gj + 1 <= gi1 && gj + 1 >= rsv1) ? exp2f(S[n][3]) : 0.0f;
                    lsum0 += p0 + p1;
                    lsum1 += p2 + p3;
                    S[n][0] = p0; S[n][1] = p1; S[n][2] = p2; S[n][3] = p3;
                }
            }

            // ---- O += P V ----
            #pragma unroll
            for (int kc = 0; kc < 4; kc++) {
                uint32_t ah0 = cvt2h(S[2*kc][0],   S[2*kc][1]);
                uint32_t ah1 = cvt2h(S[2*kc][2],   S[2*kc][3]);
                uint32_t ah2 = cvt2h(S[2*kc+1][0], S[2*kc+1][1]);
                uint32_t ah3 = cvt2h(S[2*kc+1][2], S[2*kc+1][3]);
                const uint32_t vrow = stage + vb_off
                                      + (uint32_t)((sub * 64 + kc * 16) * RSTR);
                #pragma unroll
                for (int p = 0; p < 8; p++) {
                    uint32_t vf0, vf1, vf2, vf3;
                    ldsm_x4t(vf0, vf1, vf2, vf3, vrow + p * 32);
                    mma16816(O[2*p],   ah0,ah1,ah2,ah3, vf0, vf1);
                    mma16816(O[2*p+1], ah0,ah1,ah2,ah3, vf2, vf3);
                }
            }
        }
    }

    // ---- row-sum reduce across quad, normalize, store ----
    lsum0 += __shfl_xor_sync(0xffffffffu, lsum0, 1);
    lsum0 += __shfl_xor_sync(0xffffffffu, lsum0, 2);
    lsum1 += __shfl_xor_sync(0xffffffffu, lsum1, 1);
    lsum1 += __shfl_xor_sync(0xffffffffu, lsum1, 2);
    const float inv0 = 1.0f / lsum0;
    const float inv1 = 1.0f / lsum1;

    float* o0 = out + (size_t)gi0 * (HQ * D) + h * D + 2 * (lane & 3);
    float* o1 = out + (size_t)gi1 * (HQ * D) + h * D + 2 * (lane & 3);
    #pragma unroll
    for (int n = 0; n < 16; n++) {
        *(float2*)(o0 + n * 8) = make_float2(O[n][0] * inv0, O[n][1] * inv0);
        *(float2*)(o1 + n * 8) = make_float2(O[n][2] * inv1, O[n][3] * inv1);
    }
}

extern "C" void kernel_launch(void* const* d_in, const int* in_sizes, int n_in,
                              void* d_out, int out_size)
{
    const float* q   = (const float*)d_in[0];
    const float* k   = (const float*)d_in[1];
    const float* v   = (const float*)d_in[2];
    const int*   pos = (const int*)d_in[3];
    float* out = (float*)d_out;

    const int T  = in_sizes[3];
    const int n4 = T * HKV * D / 4;

    cvt_kv_kernel<<<(n4 + 255) / 256, 256>>>(k, v, n4);

    cudaFuncSetAttribute(fa_hmma_bk128_kernel,
                         cudaFuncAttributeMaxDynamicSharedMemorySize,
                         SMEM_BYTES);
    dim3 grid(T / BQ, HQ);
    fa_hmma_bk128_kernel<<<grid, NT, SMEM_BYTES>>>(q, pos, out);
}

// round 14
// speedup vs baseline: 1.1532x; 1.0424x over previous
#include <cuda_runtime.h>
#include <cuda_fp16.h>
#include <stdint.h>

#define HQ 16
#define HKV 8
#define D 128
#define BQ 128
#define BKV 128        // staged kv rows per pipeline step (2 x 64 sub-tiles)
#define NT 256
#define TMAX 4096
// attention scale with log2(e) folded in: exp(x) = exp2(x*log2e)
#define QSCALE (0.08838834764831845f * 1.4426950408889634f)

#define RSTR 272       // bytes per smem row (136 fp16: 128 data + 8 pad)

// SMEM: Q | stage0 | stage1 ; stage = K 128*272 | V 128*272
#define SM_QH 0
#define SM_VOF 34816                      // V offset within a stage
#define SM_ST(i) (34816 + (i) * 69632)
#define SMEM_BYTES (34816 + 2 * 69632)    // 174080

// preconverted fp16 K/V (graph-safe scratch)
__device__ __half g_k16[(size_t)TMAX * HKV * D];
__device__ __half g_v16[(size_t)TMAX * HKV * D];

__device__ __forceinline__ uint32_t smem_u32(const void* p) {
    uint32_t a;
    asm("{ .reg .u64 t; cvta.to.shared.u64 t, %1; cvt.u32.u64 %0, t; }" : "=r"(a) : "l"(p));
    return a;
}
__device__ __forceinline__ void ldsm_x4(uint32_t& r0, uint32_t& r1, uint32_t& r2,
                                        uint32_t& r3, uint32_t addr) {
    asm volatile("ldmatrix.sync.aligned.m8n8.x4.shared.b16 {%0,%1,%2,%3}, [%4];"
                 : "=r"(r0), "=r"(r1), "=r"(r2), "=r"(r3) : "r"(addr));
}
__device__ __forceinline__ void ldsm_x4t(uint32_t& r0, uint32_t& r1, uint32_t& r2,
                                         uint32_t& r3, uint32_t addr) {
    asm volatile("ldmatrix.sync.aligned.m8n8.x4.trans.shared.b16 {%0,%1,%2,%3}, [%4];"
                 : "=r"(r0), "=r"(r1), "=r"(r2), "=r"(r3) : "r"(addr));
}
__device__ __forceinline__ void mma16816(float* c, uint32_t a0, uint32_t a1,
                                         uint32_t a2, uint32_t a3,
                                         uint32_t b0, uint32_t b1) {
    asm volatile("mma.sync.aligned.m16n8k16.row.col.f32.f16.f16.f32 "
                 "{%0,%1,%2,%3}, {%4,%5,%6,%7}, {%8,%9}, {%0,%1,%2,%3};"
                 : "+f"(c[0]), "+f"(c[1]), "+f"(c[2]), "+f"(c[3])
                 : "r"(a0), "r"(a1), "r"(a2), "r"(a3), "r"(b0), "r"(b1));
}
__device__ __forceinline__ uint32_t cvt2h(float x, float y) {
    __half2 H = __floats2half2_rn(x, y);
    return *(uint32_t*)&H;
}

// ---- pre-pass: fp32 K/V -> fp16 global buffers ----
__global__ void __launch_bounds__(256, 4)
cvt_kv_kernel(const float* __restrict__ k, const float* __restrict__ v, int n4)
{
    int i = blockIdx.x * blockDim.x + threadIdx.x;
    if (i < n4) {
        float4 a = ((const float4*)k)[i];
        ((__half2*)g_k16)[2 * i]     = __floats2half2_rn(a.x, a.y);
        ((__half2*)g_k16)[2 * i + 1] = __floats2half2_rn(a.z, a.w);
        float4 b = ((const float4*)v)[i];
        ((__half2*)g_v16)[2 * i]     = __floats2half2_rn(b.x, b.y);
        ((__half2*)g_v16)[2 * i + 1] = __floats2half2_rn(b.z, b.w);
    }
}

__global__ void __launch_bounds__(NT, 1)
fa_hmma_qreg_kernel(const float* __restrict__ q,
                    const int*   __restrict__ pos,
                    float*       __restrict__ out)
{
    extern __shared__ __align__(16) unsigned char smem[];
    const uint32_t sb = smem_u32(smem);

    const int tid  = threadIdx.x;
    const int wid  = tid >> 5;
    const int lane = tid & 31;
    const int bq0  = (gridDim.x - 1 - blockIdx.x) * BQ;   // longest-first
    const int h    = blockIdx.y;
    const int kvh  = h >> 1;

    const int kb0 = (bq0 - pos[bq0]) & ~(BKV - 1);

    // cp.async duty
    const int c0t = tid & 1;
    const int c0r = (tid >> 1) & 127;
    const __half* cp_src0a = (c0t ? g_v16 : g_k16) + ((size_t)c0r * HKV + kvh) * D;
    const __half* cp_src0b = cp_src0a + 64;
    const uint32_t cp_dsta = (uint32_t)(c0t * SM_VOF + c0r * RSTR);
    const uint32_t cp_dstb = cp_dsta + 128;

    // ---- prologue: prefetch tile 0 into stage 0 ----
    {
        const size_t off = (size_t)kb0 * (HKV * D);
        const uint32_t dst = sb + SM_ST(0);
        #pragma unroll
        for (int u = 0; u < 8; u++)
            asm volatile("cp.async.cg.shared.global [%0], [%1], 16;"
                         :: "r"(dst + cp_dsta + u * 16), "l"(cp_src0a + off + u * 8));
        #pragma unroll
        for (int u = 0; u < 8; u++)
            asm volatile("cp.async.cg.shared.global [%0], [%1], 16;"
                         :: "r"(dst + cp_dstb + u * 16), "l"(cp_src0b + off + u * 8));
        asm volatile("cp.async.commit_group;" ::: "memory");
    }

    // ---- stage Q (scaled, single fp16) ----
    {
        const int tok  = tid >> 1;
        const int dseg = (tid & 1) * 64;
        const float* qr = q + (size_t)(bq0 + tok) * (HQ * D) + h * D + dseg;
        unsigned char* qhrow = smem + SM_QH + tok * RSTR + dseg * 2;
        #pragma unroll
        for (int c8 = 0; c8 < 8; c8++) {
            float4 a = *(const float4*)(qr + c8 * 8);
            float4 b = *(const float4*)(qr + c8 * 8 + 4);
            *(uint4*)(qhrow + c8 * 16) =
                make_uint4(cvt2h(a.x * QSCALE, a.y * QSCALE),
                           cvt2h(a.z * QSCALE, a.w * QSCALE),
                           cvt2h(b.x * QSCALE, b.y * QSCALE),
                           cvt2h(b.z * QSCALE, b.w * QSCALE));
        }
    }
    __syncthreads();   // Q visible

    // ---- Q fragments -> registers (once) ----
    const uint32_t qa_off = (uint32_t)((16 * wid + (lane & 15)) * RSTR + (lane >> 4) * 16);
    uint32_t qf[8][4];
    #pragma unroll
    for (int kk = 0; kk < 8; kk++)
        ldsm_x4(qf[kk][0], qf[kk][1], qf[kk][2], qf[kk][3],
                sb + SM_QH + qa_off + kk * 32);

    // per-lane row metadata (C-fragment rows)
    const int gi0  = bq0 + 16 * wid + (lane >> 2);
    const int gi1  = gi0 + 8;
    const int rsv0 = gi0 - pos[gi0];
    const int rsv1 = gi1 - pos[gi1];
    // warp-uniform bounds for tile classification
    const int rowmin = bq0 + 16 * wid;
    const int rowmax = rowmin + 15;
    const int rsvmin = rowmin - pos[rowmin];
    const int rsvmax = rowmax - pos[rowmax];

    // fragment smem byte-offset bases (per lane)
    const uint32_t kb_off = (uint32_t)((((lane >> 4) & 1) * 8 + (lane & 7)) * RSTR
                                       + ((lane >> 3) & 1) * 16);
    const uint32_t vb_off = (uint32_t)((((lane >> 3) & 1) * 8 + (lane & 7)) * RSTR
                                       + SM_VOF + ((lane >> 4) & 1) * 16);

    // ones-column B fragment for lsum-via-MMA (col 0 of an N=8 tile is all 1.0)
    const uint32_t bone = ((lane >> 2) == 0) ? 0x3C003C00u : 0u;

    float O[16][4];
    #pragma unroll
    for (int n = 0; n < 16; n++)
        #pragma unroll
        for (int e = 0; e < 4; e++) O[n][e] = 0.0f;
    float Lacc[4] = {0.0f, 0.0f, 0.0f, 0.0f};

    int it = 0;
    for (int kb = kb0; kb < bq0 + BQ; kb += BKV, ++it) {
        asm volatile("cp.async.wait_group 0;" ::: "memory");
        __syncthreads();   // copies visible; prev-stage reads complete

        const uint32_t stage = sb + SM_ST(it & 1);
        if (kb + BKV < bq0 + BQ) {
            const size_t off = (size_t)(kb + BKV) * (HKV * D);
            const uint32_t dst = sb + SM_ST((it + 1) & 1);
            #pragma unroll
            for (int u = 0; u < 8; u++)
                asm volatile("cp.async.cg.shared.global [%0], [%1], 16;"
                             :: "r"(dst + cp_dsta + u * 16), "l"(cp_src0a + off + u * 8));
            #pragma unroll
            for (int u = 0; u < 8; u++)
                asm volatile("cp.async.cg.shared.global [%0], [%1], 16;"
                             :: "r"(dst + cp_dstb + u * 16), "l"(cp_src0b + off + u * 8));
            asm volatile("cp.async.commit_group;" ::: "memory");
        }

        #pragma unroll
        for (int sub = 0; sub < 2; sub++) {
            const int kbs = kb + sub * 64;
            if (kbs > rowmax) continue;          // entirely beyond diagonal
            if (kbs + 63 < rsvmin) continue;     // entirely before segment
            const bool fast = (kbs + 63 <= rowmin) && (kbs >= rsvmax);
            const uint32_t subk = stage + (uint32_t)(sub * 64 * RSTR);

            // ---- S = Q K^T (Q fragments in registers) ----
            float S[8][4];
            #pragma unroll
            for (int n = 0; n < 8; n++)
                #pragma unroll
                for (int e = 0; e < 4; e++) S[n][e] = 0.0f;

            #pragma unroll
            for (int kk = 0; kk < 8; kk++) {
                uint32_t kf[4][4];
                #pragma unroll
                for (int np = 0; np < 4; np++)
                    ldsm_x4(kf[np][0], kf[np][1], kf[np][2], kf[np][3],
                            subk + kb_off + np * (16 * RSTR) + kk * 32);
                #pragma unroll
                for (int np = 0; np < 4; np++) {
                    mma16816(S[2*np],   qf[kk][0],qf[kk][1],qf[kk][2],qf[kk][3],
                             kf[np][0], kf[np][1]);
                    mma16816(S[2*np+1], qf[kk][0],qf[kk][1],qf[kk][2],qf[kk][3],
                             kf[np][2], kf[np][3]);
                }
            }

            // ---- exp2 (fast: unmasked; else mask boundary) ----
            if (fast) {
                #pragma unroll
                for (int n = 0; n < 8; n++) {
                    S[n][0] = exp2f(S[n][0]);
                    S[n][1] = exp2f(S[n][1]);
                    S[n][2] = exp2f(S[n][2]);
                    S[n][3] = exp2f(S[n][3]);
                }
            } else {
                #pragma unroll
                for (int n = 0; n < 8; n++) {
                    const int gj = kbs + n * 8 + 2 * (lane & 3);
                    S[n][0] = (gj     <= gi0 && gj     >= rsv0) ? exp2f(S[n][0]) : 0.0f;
                    S[n][1] = (gj + 1 <= gi0 && gj + 1 >= rsv0) ? exp2f(S[n][1]) : 0.0f;
                    S[n][2] = (gj     <= gi1 && gj     >= rsv1) ? exp2f(S[n][2]) : 0.0f;
                    S[n][3] = (gj + 1 <= gi1 && gj + 1 >= rsv1) ? exp2f(S[n][3]) : 0.0f;
                }
            }

            // ---- O += P V ; lsum += P (ones-column MMA) ----
            #pragma unroll
            for (int kc = 0; kc < 4; kc++) {
                uint32_t ah0 = cvt2h(S[2*kc][0],   S[2*kc][1]);
                uint32_t ah1 = cvt2h(S[2*kc][2],   S[2*kc][3]);
                uint32_t ah2 = cvt2h(S[2*kc+1][0], S[2*kc+1][1]);
                uint32_t ah3 = cvt2h(S[2*kc+1][2], S[2*kc+1][3]);
                mma16816(Lacc, ah0,ah1,ah2,ah3, bone, bone);
                const uint32_t vrow = stage + vb_off
                                      + (uint32_t)((sub * 64 + kc * 16) * RSTR);
                #pragma unroll
                for (int p = 0; p < 8; p++) {
                    uint32_t vf0, vf1, vf2, vf3;
                    ldsm_x4t(vf0, vf1, vf2, vf3, vrow + p * 32);
                    mma16816(O[2*p],   ah0,ah1,ah2,ah3, vf0, vf1);
                    mma16816(O[2*p+1], ah0,ah1,ah2,ah3, vf2, vf3);
                }
            }
        }
    }

    // ---- row sums live in Lacc col 0 (lanes with lane%4==0); broadcast ----
    const int base = lane & ~3;
    const float inv0 = 1.0f / __shfl_sync(0xffffffffu, Lacc[0], base);
    const float inv1 = 1.0f / __shfl_sync(0xffffffffu, Lacc[2], base);

    float* o0 = out + (size_t)gi0 * (HQ * D) + h * D + 2 * (lane & 3);
    float* o1 = out + (size_t)gi1 * (HQ * D) + h * D + 2 * (lane & 3);
    #pragma unroll
    for (int n = 0; n < 16; n++) {
        *(float2*)(o0 + n * 8) = make_float2(O[n][0] * inv0, O[n][1] * inv0);
        *(float2*)(o1 + n * 8) = make_float2(O[n][2] * inv1, O[n][3] * inv1);
    }
}

extern "C" void kernel_launch(void* const* d_in, const int* in_sizes, int n_in,
                              void* d_out, int out_size)
{
    const float* q   = (const float*)d_in[0];
    const float* k   = (const float*)d_in[1];
    const float* v   = (const float*)d_in[2];
    const int*   pos = (const int*)d_in[3];
    float* out = (float*)d_out;

    const int T  = in_sizes[3];
    const int n4 = T * HKV * D / 4;

    cvt_kv_kernel<<<(n4 + 255) / 256, 256>>>(k, v, n4);

    cudaFuncSetAttribute(fa_hmma_qreg_kernel,
                         cudaFuncAttributeMaxDynamicSharedMemorySize,
                         SMEM_BYTES);
    dim3 grid(T / BQ, HQ);
    fa_hmma_qreg_kernel<<<grid, NT, SMEM_BYTES>>>(q, pos, out);
}